// round 16
// baseline (speedup 1.0000x reference)
#include <cuda_runtime.h>
#include <stdint.h>
#include <math.h>

#define NN 100000
#define NE 3200000
#define NBLK 391          // ceil(NN/256)
#define G_NPB 32          // nodes per block in gather kernels (256 thr / 8)
#define G_NBLK ((NN + G_NPB - 1) / G_NPB)

// ---------------- scratch (device globals: no allocation allowed) ----------
__device__ int   g_cnt[NN];        // in-degree histogram; re-zeroed by gather2
__device__ int   g_off[NN];        // CSR base per node (chunk-relocated)
__device__ int   g_cur[NN];        // fill cursors
__device__ int   g_total;          // bump allocator for chunk bases
__device__ int   g_csr_src[NE];    // CSR: src ids grouped by dst
__device__ float g_dinv[NN];
__device__ float g_h1s[NN * 16];   // x@W1, scaled in-place by dinv[row] in K3
__device__ float g_h2s[NN * 8];    // (relu-out @ W2) * dinv[row], padded to 8

__device__ __forceinline__ void cp_async16(unsigned dst_smem, const void* src) {
    asm volatile("cp.async.cg.shared.global [%0], [%1], 16;"
                 :: "r"(dst_smem), "l"(src) : "memory");
}
__device__ __forceinline__ void cp_commit() {
    asm volatile("cp.async.commit_group;" ::: "memory");
}
template <int N>
__device__ __forceinline__ void cp_wait() {
    asm volatile("cp.async.wait_group %0;" :: "n"(N) : "memory");
}

// split f32 into exact tf32 high part + residual
__device__ __forceinline__ void split_tf32(float v, unsigned& hi, unsigned& lo) {
    unsigned u = __float_as_uint(v) & 0xFFFFE000u;
    hi = u;
    lo = __float_as_uint(v - __uint_as_float(u));
}

__device__ __forceinline__ void mma_tf32(float* d,
                                         unsigned a0, unsigned a1, unsigned a2, unsigned a3,
                                         unsigned b0, unsigned b1) {
    asm("mma.sync.aligned.m16n8k8.row.col.f32.tf32.tf32.f32 "
        "{%0,%1,%2,%3},{%4,%5,%6,%7},{%8,%9},{%0,%1,%2,%3};"
        : "+f"(d[0]), "+f"(d[1]), "+f"(d[2]), "+f"(d[3])
        : "r"(a0), "r"(a1), "r"(a2), "r"(a3), "r"(b0), "r"(b1));
}

// per-warp dtype detect: high words of first 32 int64 entries all zero -> 64-bit
__device__ __forceinline__ bool detect64(const void* ei) {
    const unsigned* u = (const unsigned*)ei;
    unsigned hv = __ldg(u + 2 * (threadIdx.x & 31) + 1);
    return !__any_sync(0xFFFFFFFFu, hv != 0);
}

// ---------------- GEMM tile geometry ----------------------------------------
#define GM_THR   256
#define GM_RPW   48
#define GM_ROWS  384
#define GM_KC    16
#define GM_NCH   (512 / GM_KC)
#define GM_XST   (GM_KC + 4)
#define GM_XBUF  (GM_ROWS * GM_XST)
#define GM_GRID  ((NN + GM_ROWS - 1) / GM_ROWS)   // 261
#define K1_HIST  35                                // co-resident hist CTAs
#define K1_GRID  (GM_GRID + K1_HIST)               // 296 = 148 SMs * 2 slots
#define K1_SMEM  ((512 * 16 + 2 * GM_XBUF) * 4)    // 94208 B

// ---------------- K1: gemm1 (blocks < GM_GRID)  ||  hist (rest) -------------
__global__ __launch_bounds__(GM_THR) void mega1_kernel(const float* __restrict__ x,
                                                       const float* __restrict__ W1,
                                                       const void* __restrict__ ei) {
    extern __shared__ float smem[];
    int tid = threadIdx.x;

    if (blockIdx.x >= GM_GRID) {
        // ---------------- histogram path ----------------
        if (blockIdx.x == GM_GRID && tid == 0) g_total = 0;  // consumed by scan
        bool is64 = detect64(ei);
        int t = (blockIdx.x - GM_GRID) * GM_THR + tid;       // 0..8959
        const int stride = K1_HIST * GM_THR * 4;             // 35840 edges/iter
        for (int e = t * 4; e < NE; e += stride) {
            int d0, d1, d2, d3;
            if (is64) {
                const long long* p = (const long long*)ei + NE + e;
                longlong2 v0 = __ldg((const longlong2*)p);
                longlong2 v1 = __ldg((const longlong2*)(p + 2));
                d0 = (int)v0.x; d1 = (int)v0.y; d2 = (int)v1.x; d3 = (int)v1.y;
            } else {
                int4 v = __ldg((const int4*)((const int*)ei + NE + e));
                d0 = v.x; d1 = v.y; d2 = v.z; d3 = v.w;
            }
            atomicAdd(&g_cnt[d0], 1);   // return unused -> RED
            atomicAdd(&g_cnt[d1], 1);
            atomicAdd(&g_cnt[d2], 1);
            atomicAdd(&g_cnt[d3], 1);
        }
        return;
    }

    // ---------------- gemm path ----------------
    float* ws = smem;
    float* xs = smem + 512 * 16;
    int wq   = tid >> 5;
    int lane = tid & 31;
    int gid  = lane >> 2;
    int tig  = lane & 3;
    int row0 = blockIdx.x * GM_ROWS;

    {
        const float4* Wv = (const float4*)W1;
        float4* wsv = (float4*)ws;
#pragma unroll
        for (int i = 0; i < 8; i++) wsv[tid + GM_THR * i] = Wv[tid + GM_THR * i];
    }

    unsigned xs_base = (unsigned)__cvta_generic_to_shared(xs);

    auto issue_copy = [&](int c, int buf) {
        const float4* xv = (const float4*)x;
        unsigned dst0 = xs_base + buf * (GM_XBUF * 4);
#pragma unroll
        for (int i = 0; i < 6; i++) {
            int idx = tid + GM_THR * i;
            int r = idx >> 2, q = idx & 3;
            int gr = row0 + r; if (gr >= NN) gr = NN - 1;
            cp_async16(dst0 + (r * GM_XST + 4 * q) * 4,
                       xv + (long)gr * 128 + c * (GM_KC / 4) + q);
        }
        cp_commit();
    };

    issue_copy(0, 0);

    float acc[3][2][4];
#pragma unroll
    for (int mt = 0; mt < 3; mt++)
#pragma unroll
        for (int nt = 0; nt < 2; nt++)
#pragma unroll
            for (int q = 0; q < 4; q++) acc[mt][nt][q] = 0.0f;

    for (int c = 0; c < GM_NCH; c++) {
        if (c + 1 < GM_NCH) { issue_copy(c + 1, (c + 1) & 1); cp_wait<1>(); }
        else                { cp_wait<0>(); }
        __syncthreads();

        const float* xb = xs + (c & 1) * GM_XBUF;
        int kbase = c * GM_KC;
#pragma unroll
        for (int ks = 0; ks < 2; ks++) {
            int krow = kbase + ks * 8;
            unsigned bhi[2][2], blo[2][2];
#pragma unroll
            for (int nt = 0; nt < 2; nt++) {
                float w0 = ws[(krow + tig) * 16 + gid + 8 * nt];
                float w1 = ws[(krow + tig + 4) * 16 + gid + 8 * nt];
                split_tf32(w0, bhi[nt][0], blo[nt][0]);
                split_tf32(w1, bhi[nt][1], blo[nt][1]);
            }
#pragma unroll
            for (int mt = 0; mt < 3; mt++) {
                int rl = wq * GM_RPW + mt * 16 + gid;
                const float* xr = xb + rl * GM_XST + ks * 8 + tig;
                float a0 = xr[0];
                float a1 = xr[8 * GM_XST];
                float a2 = xr[4];
                float a3 = xr[8 * GM_XST + 4];
                unsigned ah0, al0, ah1, al1, ah2, al2, ah3, al3;
                split_tf32(a0, ah0, al0);
                split_tf32(a1, ah1, al1);
                split_tf32(a2, ah2, al2);
                split_tf32(a3, ah3, al3);
#pragma unroll
                for (int nt = 0; nt < 2; nt++) {
                    mma_tf32(acc[mt][nt], ah0, ah1, ah2, ah3, bhi[nt][0], bhi[nt][1]);
                    mma_tf32(acc[mt][nt], al0, al1, al2, al3, bhi[nt][0], bhi[nt][1]);
                    mma_tf32(acc[mt][nt], ah0, ah1, ah2, ah3, blo[nt][0], blo[nt][1]);
                }
            }
        }
        __syncthreads();
    }

#pragma unroll
    for (int mt = 0; mt < 3; mt++) {
        int r0 = row0 + wq * GM_RPW + mt * 16 + gid;
        int r1 = r0 + 8;
#pragma unroll
        for (int nt = 0; nt < 2; nt++) {
            int cb = 8 * nt + 2 * tig;
            if (r0 < NN)
                *(float2*)(g_h1s + (long)r0 * 16 + cb) = make_float2(acc[mt][nt][0], acc[mt][nt][1]);
            if (r1 < NN)
                *(float2*)(g_h1s + (long)r1 * 16 + cb) = make_float2(acc[mt][nt][2], acc[mt][nt][3]);
        }
    }
}

// ---------------- K2: single-pass scan + dinv (warp-shuffle) ----------------
__global__ __launch_bounds__(256) void scan_kernel() {
    __shared__ int wsum[8];
    __shared__ int wbase[8];
    __shared__ int base_sh;
    int tid = threadIdx.x, wid = tid >> 5, lane = tid & 31;
    int t = blockIdx.x * 256 + tid;
    int c = (t < NN) ? g_cnt[t] : 0;

    int sc = c;
#pragma unroll
    for (int d = 1; d < 32; d <<= 1) {
        int n = __shfl_up_sync(0xFFFFFFFFu, sc, d);
        if (lane >= d) sc += n;
    }
    if (lane == 31) wsum[wid] = sc;
    __syncthreads();
    if (wid == 0) {
        int v = (lane < 8) ? wsum[lane] : 0;
        int s = v;
#pragma unroll
        for (int d = 1; d < 8; d <<= 1) {
            int n = __shfl_up_sync(0xFFFFFFFFu, s, d);
            if (lane >= d) s += n;
        }
        if (lane < 8) wbase[lane] = s - v;
        if (lane == 7) base_sh = atomicAdd(&g_total, s);
    }
    __syncthreads();
    if (t < NN) {
        int off = base_sh + wbase[wid] + sc - c;
        g_off[t] = off;
        g_cur[t] = off;
        g_dinv[t] = rsqrtf((float)c + 1.0f);   // +1 = self loop
    }
}

// ---------------- K3: scale (blocks < NBLK)  ||  CSR fill (rest) ------------
#define K3_FILL  3125                            // ceil(NE / (256*4)) fill CTAs
#define K3_GRID  (NBLK + K3_FILL)

__global__ __launch_bounds__(256) void mega2_kernel(const void* __restrict__ ei) {
    int tid = threadIdx.x;
    if (blockIdx.x < NBLK) {
        // ---------------- scale path: h1s[i] *= dinv[i] ----------------
        int i = blockIdx.x * 256 + tid;
        if (i >= NN) return;
        float di = g_dinv[i];
        float4* p = (float4*)(g_h1s + (long)i * 16);
#pragma unroll
        for (int q = 0; q < 4; q++) {
            float4 v = p[q];
            p[q] = make_float4(v.x * di, v.y * di, v.z * di, v.w * di);
        }
        return;
    }
    // ---------------- fill path ----------------
    bool is64 = detect64(ei);
    int e = ((blockIdx.x - NBLK) * 256 + tid) * 4;
    if (e >= NE) return;
    int s0, s1, s2, s3, d0, d1, d2, d3;
    if (is64) {
        const long long* p = (const long long*)ei;
        longlong2 a0 = __ldg((const longlong2*)(p + e));
        longlong2 a1 = __ldg((const longlong2*)(p + e + 2));
        longlong2 b0 = __ldg((const longlong2*)(p + NE + e));
        longlong2 b1 = __ldg((const longlong2*)(p + NE + e + 2));
        s0 = (int)a0.x; s1 = (int)a0.y; s2 = (int)a1.x; s3 = (int)a1.y;
        d0 = (int)b0.x; d1 = (int)b0.y; d2 = (int)b1.x; d3 = (int)b1.y;
    } else {
        const int* p = (const int*)ei;
        int4 a = __ldg((const int4*)(p + e));
        int4 b = __ldg((const int4*)(p + NE + e));
        s0 = a.x; s1 = a.y; s2 = a.z; s3 = a.w;
        d0 = b.x; d1 = b.y; d2 = b.z; d3 = b.w;
    }
    g_csr_src[atomicAdd(&g_cur[d0], 1)] = s0;
    g_csr_src[atomicAdd(&g_cur[d1], 1)] = s1;
    g_csr_src[atomicAdd(&g_cur[d2], 1)] = s2;
    g_csr_src[atomicAdd(&g_cur[d3], 1)] = s3;
}

// ---------------- gather1 (+fused post1), 8 lanes per node -----------------
__global__ __launch_bounds__(256) void gather1_kernel(const float* __restrict__ b1,
                                                      const float* __restrict__ W2) {
    __shared__ float w2s[112];
    __shared__ float b1s[16];
    __shared__ float ts[G_NPB][18];
    int tid = threadIdx.x;
    if (tid < 112) w2s[tid] = W2[tid];
    if (tid < 16)  b1s[tid] = b1[tid];
    __syncthreads();

    int g = tid >> 3, l = tid & 7;
    int lane = tid & 31;
    unsigned gmask = 0xFFu << (lane & ~7);
    int i = blockIdx.x * G_NPB + g;
    bool valid = (i < NN);

    int beg = 0, deg = 0;
    if (valid) { beg = g_off[i]; deg = g_cnt[i]; }
    int cend = beg + (deg & ~7);
    int rem  = deg & 7;

    float ax = 0.0f, ay = 0.0f;
    for (int c = beg; c < cend; c += 8) {
        int idx = __ldg(&g_csr_src[c + l]);
#pragma unroll
        for (int t = 0; t < 8; t++) {
            int s = __shfl_sync(gmask, idx, t, 8);
            float2 v = *(const float2*)(g_h1s + (long)s * 16 + 2 * l);
            ax += v.x; ay += v.y;
        }
    }
    if (rem) {
        int idx = (l < rem) ? __ldg(&g_csr_src[cend + l]) : 0;
#pragma unroll
        for (int t = 0; t < 8; t++) {
            int s = __shfl_sync(gmask, idx, t, 8);
            if (t < rem) {
                float2 v = *(const float2*)(g_h1s + (long)s * 16 + 2 * l);
                ax += v.x; ay += v.y;
            }
        }
    }

    if (valid) {
        float di = g_dinv[i];
        float2 h = *(const float2*)(g_h1s + (long)i * 16 + 2 * l);
        ts[g][2 * l]     = fmaxf(fmaf(di, ax + h.x, b1s[2 * l]),     0.0f);
        ts[g][2 * l + 1] = fmaxf(fmaf(di, ay + h.y, b1s[2 * l + 1]), 0.0f);
    }
    __syncthreads();

    if (valid) {
        float o = 0.0f;
        if (l < 7) {
            float di = g_dinv[i];
#pragma unroll
            for (int j2 = 0; j2 < 16; j2++) o = fmaf(ts[g][j2], w2s[j2 * 7 + l], o);
            o *= di;
        }
        g_h2s[(long)i * 8 + l] = o;   // lane 7 writes the 0 pad
    }
}

// ---------------- gather2 (+fused post2: log_softmax), 8 lanes per node ----
// Also re-zeroes g_cnt[i] (keeps globals clean for the next replay).
__global__ __launch_bounds__(256) void gather2_kernel(const float* __restrict__ b2,
                                                      float* __restrict__ out) {
    int tid = threadIdx.x;
    int g = tid >> 3, l = tid & 7;
    int lane = tid & 31;
    unsigned gmask = 0xFFu << (lane & ~7);
    int i = blockIdx.x * G_NPB + g;
    bool valid = (i < NN);

    int beg = 0, deg = 0;
    if (valid) { beg = g_off[i]; deg = g_cnt[i]; }
    int cend = beg + (deg & ~7);
    int rem  = deg & 7;

    float acc = 0.0f;
    for (int c = beg; c < cend; c += 8) {
        int idx = __ldg(&g_csr_src[c + l]);
#pragma unroll
        for (int t = 0; t < 8; t++) {
            int s = __shfl_sync(gmask, idx, t, 8);
            acc += __ldg(&g_h2s[(long)s * 8 + l]);
        }
    }
    if (rem) {
        int idx = (l < rem) ? __ldg(&g_csr_src[cend + l]) : 0;
#pragma unroll
        for (int t = 0; t < 8; t++) {
            int s = __shfl_sync(gmask, idx, t, 8);
            if (t < rem) acc += __ldg(&g_h2s[(long)s * 8 + l]);
        }
    }

    if (valid && l == 0) g_cnt[i] = 0;   // restore invariant for next call

    float di = valid ? g_dinv[i] : 0.0f;
    float h  = valid ? g_h2s[(long)i * 8 + l] : 0.0f;
    float o  = (l < 7) ? fmaf(di, acc + h, __ldg(b2 + l)) : -3.0e38f;

    float m = o;
#pragma unroll
    for (int d = 1; d < 8; d <<= 1) m = fmaxf(m, __shfl_xor_sync(gmask, m, d, 8));
    float e = (l < 7) ? expf(o - m) : 0.0f;
    float s = e;
#pragma unroll
    for (int d = 1; d < 8; d <<= 1) s += __shfl_xor_sync(gmask, s, d, 8);
    float lse = logf(s);

    if (valid && l < 7) out[(long)i * 7 + l] = o - m - lse;
}

// ---------------- host ------------------------------------------------------
extern "C" void kernel_launch(void* const* d_in, const int* in_sizes, int n_in,
                              void* d_out, int out_size) {
    const float* x  = (const float*)d_in[0];
    const void*  ei = d_in[1];
    const float* W1 = (const float*)d_in[2];
    const float* b1 = (const float*)d_in[3];
    const float* W2 = (const float*)d_in[4];
    const float* b2 = (const float*)d_in[5];
    float* out = (float*)d_out;

    cudaFuncSetAttribute(mega1_kernel, cudaFuncAttributeMaxDynamicSharedMemorySize, K1_SMEM);
    mega1_kernel<<<K1_GRID, GM_THR, K1_SMEM>>>(x, W1, ei);   // gemm1 || hist
    scan_kernel<<<NBLK, 256>>>();
    mega2_kernel<<<K3_GRID, 256>>>(ei);                      // scale || fill
    gather1_kernel<<<G_NBLK, 256>>>(b1, W2);
    gather2_kernel<<<G_NBLK, 256>>>(b2, out);
}